// round 2
// baseline (speedup 1.0000x reference)
#include <cuda_runtime.h>
#include <math.h>

#define N_NODES 10000
#define HID 128
#define EDIM 416
#define N_EDGES 160000
#define K1 (2*HID+EDIM)              // 672
#define X_OUT_ELEMS (N_NODES*HID)    // 1,280,000

// -------- scratch (device globals; no allocations allowed) --------
__device__ __align__(128) float g_xh[N_NODES*HID];
__device__ __align__(128) float g_m[N_EDGES*HID];     // m1, then m_ij (in place)
__device__ __align__(128) float g_agg[N_NODES*HID];
__device__ __align__(128) float g_cnt[N_NODES];
__device__ __align__(128) float g_n1[N_NODES*HID];

__device__ __forceinline__ float silu_f(float x){ return x / (1.0f + __expf(-x)); }

// -------- zero agg/cnt each launch --------
__global__ void zero_kernel(){
    int i = blockIdx.x*blockDim.x + threadIdx.x;
    if (i < N_NODES*HID) g_agg[i] = 0.0f;
    if (i < N_NODES)     g_cnt[i] = 0.0f;
}

// -------- layernorm: one warp per row, float4 per lane --------
__global__ void ln_kernel(const float* __restrict__ x,
                          const float* __restrict__ g,
                          const float* __restrict__ b){
    int row = blockIdx.x*8 + threadIdx.y;
    if (row >= N_NODES) return;
    int lane = threadIdx.x;
    float4 v = ((const float4*)(x + row*HID))[lane];
    float s = v.x + v.y + v.z + v.w;
    #pragma unroll
    for (int o = 16; o > 0; o >>= 1) s += __shfl_xor_sync(0xffffffffu, s, o);
    float mu = s * (1.0f/HID);
    float dx = v.x-mu, dy = v.y-mu, dz = v.z-mu, dw = v.w-mu;
    float q = dx*dx + dy*dy + dz*dz + dw*dw;
    #pragma unroll
    for (int o = 16; o > 0; o >>= 1) q += __shfl_xor_sync(0xffffffffu, q, o);
    float rstd = rsqrtf(q*(1.0f/HID) + 1e-5f);
    float4 gg = ((const float4*)g)[lane];
    float4 bb = ((const float4*)b)[lane];
    float4 o4;
    o4.x = dx*rstd*gg.x + bb.x;
    o4.y = dy*rstd*gg.y + bb.y;
    o4.z = dz*rstd*gg.z + bb.z;
    o4.w = dw*rstd*gg.w + bb.w;
    ((float4*)(g_xh + row*HID))[lane] = o4;
}

// -------- edge MLP layer 1: m1[E,128] = silu([xh_i|xh_j|w] @ We1 + be1) --------
// Block: 64 edges x 128 outs, BK=32, 256 threads, 8x4 microtile.
__global__ void __launch_bounds__(256) edge_mlp1_kernel(const float* __restrict__ We1,
                                                        const float* __restrict__ be1,
                                                        const float* __restrict__ weight,
                                                        const int*   __restrict__ ei){
    __shared__ float sA[64*33];
    __shared__ float sB[32*128];
    __shared__ int s_ii[64], s_jj[64];
    const int tid = threadIdx.x;
    const int e0  = blockIdx.x*64;
    if (tid < 64){ s_ii[tid] = ei[e0+tid]; s_jj[tid] = ei[N_EDGES + e0 + tid]; }
    __syncthreads();   // <<< FIX: all 256 threads read s_ii/s_jj in the first tile
    const int m0 = (tid >> 5)*8;
    const int n0 = (tid & 31)*4;
    float acc[8][4];
    #pragma unroll
    for (int i = 0; i < 8; i++){ acc[i][0]=0; acc[i][1]=0; acc[i][2]=0; acc[i][3]=0; }

    for (int kt = 0; kt < K1; kt += 32){
        #pragma unroll
        for (int i = 0; i < 8; i++){
            int idx = tid + i*256;
            int r = idx >> 5, k = idx & 31;
            int kg = kt + k;
            float v;
            if (kg < HID)          v = g_xh[s_ii[r]*HID + kg];
            else if (kg < 2*HID)   v = g_xh[s_jj[r]*HID + (kg - HID)];
            else                   v = weight[(e0 + r)*EDIM + (kg - 2*HID)];
            sA[r*33 + k] = v;
        }
        #pragma unroll
        for (int i = 0; i < 16; i++){
            int idx = tid + i*256;
            int k = idx >> 7, n = idx & 127;
            sB[k*128 + n] = We1[(kt + k)*128 + n];
        }
        __syncthreads();
        #pragma unroll
        for (int kk = 0; kk < 32; kk++){
            float4 bv = *(const float4*)&sB[kk*128 + n0];
            #pragma unroll
            for (int i = 0; i < 8; i++){
                float a = sA[(m0+i)*33 + kk];
                acc[i][0] += a*bv.x; acc[i][1] += a*bv.y;
                acc[i][2] += a*bv.z; acc[i][3] += a*bv.w;
            }
        }
        __syncthreads();
    }
    float4 bias = *(const float4*)&be1[n0];
    #pragma unroll
    for (int i = 0; i < 8; i++){
        float4 o;
        o.x = silu_f(acc[i][0] + bias.x);
        o.y = silu_f(acc[i][1] + bias.y);
        o.z = silu_f(acc[i][2] + bias.z);
        o.w = silu_f(acc[i][3] + bias.w);
        *(float4*)&g_m[(e0 + m0 + i)*HID + n0] = o;
    }
}

// -------- edge MLP layer 2 + attention + gated message + segment-sum --------
__global__ void __launch_bounds__(256) edge_mlp2_kernel(const float* __restrict__ We2,
                                                        const float* __restrict__ be2,
                                                        const float* __restrict__ Wa,
                                                        const float* __restrict__ ba,
                                                        const int*   __restrict__ ei){
    __shared__ float smem[64*128];   // GEMM phase: [0,2112) = sA(64x33), [2112,6208) = sB(32x128); then m2[64][128]
    __shared__ float s_att[64];
    __shared__ int   s_ii[64];
    float* sA = smem;
    float* sB = smem + 64*33;
    const int tid = threadIdx.x;
    const int e0  = blockIdx.x*64;
    if (tid < 64) s_ii[tid] = ei[e0 + tid];
    const int m0 = (tid >> 5)*8;
    const int n0 = (tid & 31)*4;
    float acc[8][4];
    #pragma unroll
    for (int i = 0; i < 8; i++){ acc[i][0]=0; acc[i][1]=0; acc[i][2]=0; acc[i][3]=0; }

    for (int kt = 0; kt < HID; kt += 32){
        #pragma unroll
        for (int i = 0; i < 8; i++){
            int idx = tid + i*256;
            int r = idx >> 5, k = idx & 31;
            sA[r*33 + k] = g_m[(e0 + r)*HID + kt + k];
        }
        #pragma unroll
        for (int i = 0; i < 16; i++){
            int idx = tid + i*256;
            int k = idx >> 7, n = idx & 127;
            sB[k*128 + n] = We2[(kt + k)*128 + n];
        }
        __syncthreads();
        #pragma unroll
        for (int kk = 0; kk < 32; kk++){
            float4 bv = *(const float4*)&sB[kk*128 + n0];
            #pragma unroll
            for (int i = 0; i < 8; i++){
                float a = sA[(m0+i)*33 + kk];
                acc[i][0] += a*bv.x; acc[i][1] += a*bv.y;
                acc[i][2] += a*bv.z; acc[i][3] += a*bv.w;
            }
        }
        __syncthreads();
    }
    // m2 = silu(acc + bias) -> smem[64][128]
    float4 bias = *(const float4*)&be2[n0];
    #pragma unroll
    for (int i = 0; i < 8; i++){
        float4 o;
        o.x = silu_f(acc[i][0] + bias.x);
        o.y = silu_f(acc[i][1] + bias.y);
        o.z = silu_f(acc[i][2] + bias.z);
        o.w = silu_f(acc[i][3] + bias.w);
        *(float4*)&smem[(m0+i)*128 + n0] = o;
    }
    __syncthreads();
    // attention: warp w handles edges [8w, 8w+8)
    {
        int w = tid >> 5, lane = tid & 31;
        float wa0 = Wa[lane], wa1 = Wa[32+lane], wa2 = Wa[64+lane], wa3 = Wa[96+lane];
        float ba0 = ba[0];
        for (int e = w*8; e < w*8 + 8; e++){
            const float* r = &smem[e*128];
            float d = r[lane]*wa0 + r[32+lane]*wa1 + r[64+lane]*wa2 + r[96+lane]*wa3;
            #pragma unroll
            for (int o = 16; o > 0; o >>= 1) d += __shfl_xor_sync(0xffffffffu, d, o);
            if (lane == 0) s_att[e] = silu_f(d + ba0);
        }
    }
    __syncthreads();
    // m_ij = m2 * att; store + atomic segment sum
    #pragma unroll
    for (int i = 0; i < 8; i++){
        int m = m0 + i;
        float a = s_att[m];
        int node = s_ii[m];
        float4 v;
        v.x = smem[m*128 + n0 + 0]*a;
        v.y = smem[m*128 + n0 + 1]*a;
        v.z = smem[m*128 + n0 + 2]*a;
        v.w = smem[m*128 + n0 + 3]*a;
        *(float4*)&g_m[(e0 + m)*HID + n0] = v;
        atomicAdd(&g_agg[node*HID + n0 + 0], v.x);
        atomicAdd(&g_agg[node*HID + n0 + 1], v.y);
        atomicAdd(&g_agg[node*HID + n0 + 2], v.z);
        atomicAdd(&g_agg[node*HID + n0 + 3], v.w);
    }
    if (tid < 64) atomicAdd(&g_cnt[s_ii[tid]], 1.0f);
}

// -------- node MLP layer 1: n1 = silu([xh | agg/cnt] @ Wn1 + bn1) --------
__global__ void __launch_bounds__(256) node_mlp1_kernel(const float* __restrict__ Wn1,
                                                        const float* __restrict__ bn1){
    __shared__ float sA[64*33];
    __shared__ float sB[32*128];
    __shared__ float s_inv[64];
    const int tid = threadIdx.x;
    const int r0  = blockIdx.x*64;
    if (tid < 64){
        int node = min(r0 + tid, N_NODES - 1);
        float c = g_cnt[node];
        s_inv[tid] = 1.0f / ((c == 0.0f) ? 1.0f : c);
    }
    __syncthreads();
    const int m0 = (tid >> 5)*8;
    const int n0 = (tid & 31)*4;
    float acc[8][4];
    #pragma unroll
    for (int i = 0; i < 8; i++){ acc[i][0]=0; acc[i][1]=0; acc[i][2]=0; acc[i][3]=0; }

    for (int kt = 0; kt < 2*HID; kt += 32){
        #pragma unroll
        for (int i = 0; i < 8; i++){
            int idx = tid + i*256;
            int r = idx >> 5, k = idx & 31;
            int kg = kt + k;
            int node = min(r0 + r, N_NODES - 1);
            float v = (kg < HID) ? g_xh[node*HID + kg]
                                 : g_agg[node*HID + (kg - HID)] * s_inv[r];
            sA[r*33 + k] = v;
        }
        #pragma unroll
        for (int i = 0; i < 16; i++){
            int idx = tid + i*256;
            int k = idx >> 7, n = idx & 127;
            sB[k*128 + n] = Wn1[(kt + k)*128 + n];
        }
        __syncthreads();
        #pragma unroll
        for (int kk = 0; kk < 32; kk++){
            float4 bv = *(const float4*)&sB[kk*128 + n0];
            #pragma unroll
            for (int i = 0; i < 8; i++){
                float a = sA[(m0+i)*33 + kk];
                acc[i][0] += a*bv.x; acc[i][1] += a*bv.y;
                acc[i][2] += a*bv.z; acc[i][3] += a*bv.w;
            }
        }
        __syncthreads();
    }
    float4 bias = *(const float4*)&bn1[n0];
    #pragma unroll
    for (int i = 0; i < 8; i++){
        int row = r0 + m0 + i;
        if (row < N_NODES){
            float4 o;
            o.x = silu_f(acc[i][0] + bias.x);
            o.y = silu_f(acc[i][1] + bias.y);
            o.z = silu_f(acc[i][2] + bias.z);
            o.w = silu_f(acc[i][3] + bias.w);
            *(float4*)&g_n1[row*HID + n0] = o;
        }
    }
}

// -------- node MLP layer 2 + residual: xh_out = xh + silu(n1 @ Wn2 + bn2) --------
__global__ void __launch_bounds__(256) node_mlp2_kernel(const float* __restrict__ Wn2,
                                                        const float* __restrict__ bn2,
                                                        float* __restrict__ out){
    __shared__ float sA[64*33];
    __shared__ float sB[32*128];
    const int tid = threadIdx.x;
    const int r0  = blockIdx.x*64;
    const int m0 = (tid >> 5)*8;
    const int n0 = (tid & 31)*4;
    float acc[8][4];
    #pragma unroll
    for (int i = 0; i < 8; i++){ acc[i][0]=0; acc[i][1]=0; acc[i][2]=0; acc[i][3]=0; }

    for (int kt = 0; kt < HID; kt += 32){
        #pragma unroll
        for (int i = 0; i < 8; i++){
            int idx = tid + i*256;
            int r = idx >> 5, k = idx & 31;
            int node = min(r0 + r, N_NODES - 1);
            sA[r*33 + k] = g_n1[node*HID + kt + k];
        }
        #pragma unroll
        for (int i = 0; i < 16; i++){
            int idx = tid + i*256;
            int k = idx >> 7, n = idx & 127;
            sB[k*128 + n] = Wn2[(kt + k)*128 + n];
        }
        __syncthreads();
        #pragma unroll
        for (int kk = 0; kk < 32; kk++){
            float4 bv = *(const float4*)&sB[kk*128 + n0];
            #pragma unroll
            for (int i = 0; i < 8; i++){
                float a = sA[(m0+i)*33 + kk];
                acc[i][0] += a*bv.x; acc[i][1] += a*bv.y;
                acc[i][2] += a*bv.z; acc[i][3] += a*bv.w;
            }
        }
        __syncthreads();
    }
    float4 bias = *(const float4*)&bn2[n0];
    #pragma unroll
    for (int i = 0; i < 8; i++){
        int row = r0 + m0 + i;
        if (row < N_NODES){
            float4 xh4 = *(const float4*)&g_xh[row*HID + n0];
            float4 o;
            o.x = xh4.x + silu_f(acc[i][0] + bias.x);
            o.y = xh4.y + silu_f(acc[i][1] + bias.y);
            o.z = xh4.z + silu_f(acc[i][2] + bias.z);
            o.w = xh4.w + silu_f(acc[i][3] + bias.w);
            *(float4*)&out[row*HID + n0] = o;
        }
    }
}

// -------- edge out: edgeh = weight + silu(m_ij @ Wo + bo) --------
__global__ void __launch_bounds__(256) edge_out_kernel(const float* __restrict__ Wo,
                                                       const float* __restrict__ bo,
                                                       const float* __restrict__ weight,
                                                       float* __restrict__ out){
    __shared__ float sA[64*33];
    __shared__ float sB[32*128];
    const int tid = threadIdx.x;
    const int e0  = blockIdx.x*64;
    const int nb  = blockIdx.y*128;
    const int m0 = (tid >> 5)*8;
    const int n0 = (tid & 31)*4;
    float acc[8][4];
    #pragma unroll
    for (int i = 0; i < 8; i++){ acc[i][0]=0; acc[i][1]=0; acc[i][2]=0; acc[i][3]=0; }

    for (int kt = 0; kt < HID; kt += 32){
        #pragma unroll
        for (int i = 0; i < 8; i++){
            int idx = tid + i*256;
            int r = idx >> 5, k = idx & 31;
            sA[r*33 + k] = g_m[(e0 + r)*HID + kt + k];
        }
        #pragma unroll
        for (int i = 0; i < 16; i++){
            int idx = tid + i*256;
            int k = idx >> 7, n = idx & 127;
            int ng = nb + n;
            sB[k*128 + n] = (ng < EDIM) ? Wo[(kt + k)*EDIM + ng] : 0.0f;
        }
        __syncthreads();
        #pragma unroll
        for (int kk = 0; kk < 32; kk++){
            float4 bv = *(const float4*)&sB[kk*128 + n0];
            #pragma unroll
            for (int i = 0; i < 8; i++){
                float a = sA[(m0+i)*33 + kk];
                acc[i][0] += a*bv.x; acc[i][1] += a*bv.y;
                acc[i][2] += a*bv.z; acc[i][3] += a*bv.w;
            }
        }
        __syncthreads();
    }
    int n0g = nb + n0;
    if (n0g < EDIM){
        float4 bias = *(const float4*)&bo[n0g];
        #pragma unroll
        for (int i = 0; i < 8; i++){
            int e = e0 + m0 + i;
            float4 w4 = *(const float4*)&weight[e*EDIM + n0g];
            float4 o;
            o.x = w4.x + silu_f(acc[i][0] + bias.x);
            o.y = w4.y + silu_f(acc[i][1] + bias.y);
            o.z = w4.z + silu_f(acc[i][2] + bias.z);
            o.w = w4.w + silu_f(acc[i][3] + bias.w);
            *(float4*)&out[X_OUT_ELEMS + e*EDIM + n0g] = o;
        }
    }
}

extern "C" void kernel_launch(void* const* d_in, const int* in_sizes, int n_in,
                              void* d_out, int out_size){
    const float* x    = (const float*)d_in[0];
    const float* wgt  = (const float*)d_in[1];
    const float* ln_g = (const float*)d_in[2];
    const float* ln_b = (const float*)d_in[3];
    const float* We1  = (const float*)d_in[4];
    const float* be1  = (const float*)d_in[5];
    const float* We2  = (const float*)d_in[6];
    const float* be2  = (const float*)d_in[7];
    const float* Wa   = (const float*)d_in[8];
    const float* ba   = (const float*)d_in[9];
    const float* Wn1  = (const float*)d_in[10];
    const float* bn1  = (const float*)d_in[11];
    const float* Wn2  = (const float*)d_in[12];
    const float* bn2  = (const float*)d_in[13];
    const float* Wo   = (const float*)d_in[14];
    const float* bo   = (const float*)d_in[15];
    const int*   ei   = (const int*)d_in[16];
    float* out = (float*)d_out;

    zero_kernel<<<(N_NODES*HID + 255)/256, 256>>>();
    ln_kernel<<<(N_NODES + 7)/8, dim3(32, 8)>>>(x, ln_g, ln_b);
    edge_mlp1_kernel<<<N_EDGES/64, 256>>>(We1, be1, wgt, ei);
    edge_mlp2_kernel<<<N_EDGES/64, 256>>>(We2, be2, Wa, ba, ei);
    node_mlp1_kernel<<<(N_NODES + 63)/64, 256>>>(Wn1, bn1);
    node_mlp2_kernel<<<(N_NODES + 63)/64, 256>>>(Wn2, bn2, out);
    edge_out_kernel<<<dim3(N_EDGES/64, 4), 256>>>(Wo, bo, wgt, out);
}

// round 4
// speedup vs baseline: 3.0659x; 3.0659x over previous
#include <cuda_runtime.h>
#include <math.h>
#include <stdint.h>

#define N_NODES 10000
#define HID 128
#define EDIM 416
#define N_EDGES 160000
#define K1 (2*HID+EDIM)              // 672
#define X_OUT_ELEMS (N_NODES*HID)    // 1,280,000

// -------- scratch (device globals; no allocations allowed) --------
__device__ __align__(128) float g_xh[N_NODES*HID];
__device__ __align__(128) float g_m[N_EDGES*HID];     // m1, then m_ij (in place)
__device__ __align__(128) float g_agg[N_NODES*HID];
__device__ __align__(128) float g_cnt[N_NODES];
__device__ __align__(128) float g_n1[N_NODES*HID];
// transposed weights: WT[n][k] = W[k][n]
__device__ __align__(128) float g_WeT1[128*672];
__device__ __align__(128) float g_We2T[128*128];
__device__ __align__(128) float g_WoT[512*128];       // rows 416..511 zero

__device__ __forceinline__ float silu_f(float x){ return x / (1.0f + __expf(-x)); }

// tf32 convert (rna)
__device__ __forceinline__ uint32_t tf32b(float x){
    uint32_t y; asm("cvt.rna.tf32.f32 %0, %1;" : "=r"(y) : "f"(x)); return y;
}
__device__ __forceinline__ uint4 cvt4(float4 v){
    uint4 u; u.x = tf32b(v.x); u.y = tf32b(v.y); u.z = tf32b(v.z); u.w = tf32b(v.w);
    return u;
}
// m16n8k8 tf32 mma (PTX baseline, works on compute_103)
__device__ __forceinline__ void mma8(float* c, const uint32_t* a, uint32_t b0, uint32_t b1){
    asm volatile("mma.sync.aligned.m16n8k8.row.col.f32.tf32.tf32.f32 "
        "{%0,%1,%2,%3}, {%4,%5,%6,%7}, {%8,%9}, {%0,%1,%2,%3};"
        : "+f"(c[0]), "+f"(c[1]), "+f"(c[2]), "+f"(c[3])
        : "r"(a[0]), "r"(a[1]), "r"(a[2]), "r"(a[3]), "r"(b0), "r"(b1));
}

#define PADK 36   // 32 + 4 pad: conflict-free fragment LDS, 16B-aligned rows

// ================= setup kernels =================
__global__ void zero_kernel(){
    int i = blockIdx.x*blockDim.x + threadIdx.x;
    if (i < N_NODES*HID) g_agg[i] = 0.0f;
    if (i < N_NODES)     g_cnt[i] = 0.0f;
}
__global__ void tr_we1(const float* __restrict__ W){        // [672,128] -> [128,672]
    int i = blockIdx.x*blockDim.x + threadIdx.x;
    if (i < 128*672){ int n = i/672, k = i%672; g_WeT1[i] = W[k*128 + n]; }
}
__global__ void tr_we2(const float* __restrict__ W){        // [128,128] -> [128,128]
    int i = blockIdx.x*blockDim.x + threadIdx.x;
    if (i < 128*128){ int n = i/128, k = i%128; g_We2T[i] = W[k*128 + n]; }
}
__global__ void tr_wo(const float* __restrict__ W){         // [128,416] -> [512,128], pad 0
    int i = blockIdx.x*blockDim.x + threadIdx.x;
    if (i < 512*128){ int n = i/128, k = i%128; g_WoT[i] = (n < EDIM) ? W[k*EDIM + n] : 0.0f; }
}

// -------- layernorm --------
__global__ void ln_kernel(const float* __restrict__ x,
                          const float* __restrict__ g,
                          const float* __restrict__ b){
    int row = blockIdx.x*8 + threadIdx.y;
    if (row >= N_NODES) return;
    int lane = threadIdx.x;
    float4 v = ((const float4*)(x + row*HID))[lane];
    float s = v.x + v.y + v.z + v.w;
    #pragma unroll
    for (int o = 16; o > 0; o >>= 1) s += __shfl_xor_sync(0xffffffffu, s, o);
    float mu = s * (1.0f/HID);
    float dx = v.x-mu, dy = v.y-mu, dz = v.z-mu, dw = v.w-mu;
    float q = dx*dx + dy*dy + dz*dz + dw*dw;
    #pragma unroll
    for (int o = 16; o > 0; o >>= 1) q += __shfl_xor_sync(0xffffffffu, q, o);
    float rstd = rsqrtf(q*(1.0f/HID) + 1e-5f);
    float4 gg = ((const float4*)g)[lane];
    float4 bb = ((const float4*)b)[lane];
    float4 o4;
    o4.x = dx*rstd*gg.x + bb.x;
    o4.y = dy*rstd*gg.y + bb.y;
    o4.z = dz*rstd*gg.z + bb.z;
    o4.w = dw*rstd*gg.w + bb.w;
    ((float4*)(g_xh + row*HID))[lane] = o4;
}

// ============ MMA-based edge kernels: 128x128 tile, 8 warps (2x4), warp tile 64x32 ============

// fragment load helpers (sA/sB laid out [row][PADK] uint32)
#define LOAD_AFRAG(a, sA, mbase, k0, lr, lc) do { \
    (a)[0] = (sA)[((mbase) + (lr))*PADK + (k0) + (lc)]; \
    (a)[1] = (sA)[((mbase) + 8 + (lr))*PADK + (k0) + (lc)]; \
    (a)[2] = (sA)[((mbase) + (lr))*PADK + (k0) + 4 + (lc)]; \
    (a)[3] = (sA)[((mbase) + 8 + (lr))*PADK + (k0) + 4 + (lc)]; \
} while(0)

// -------- edge MLP layer 1: m1 = silu([xh_i|xh_j|w] @ We1 + be1) --------
__global__ void __launch_bounds__(256) edge_mlp1_mma(const float* __restrict__ be1,
                                                     const float* __restrict__ weight,
                                                     const int* __restrict__ ei){
    __shared__ uint32_t sA[128*PADK];
    __shared__ uint32_t sB[128*PADK];
    __shared__ float sBias[128];
    __shared__ int s_ii[128], s_jj[128];
    const int tid = threadIdx.x;
    const int e0  = blockIdx.x*128;
    if (tid < 128){
        s_ii[tid] = ei[e0 + tid];
        s_jj[tid] = ei[N_EDGES + e0 + tid];
        sBias[tid] = be1[tid];
    }
    __syncthreads();
    const int lane = tid & 31, lr = lane >> 2, lc = lane & 3;
    const int wid = tid >> 5;
    const int wm = (wid & 1)*64;     // warp row base
    const int wn = (wid >> 1)*32;    // warp col base
    float acc[4][4][4];
    #pragma unroll
    for (int i = 0; i < 4; i++)
        #pragma unroll
        for (int j = 0; j < 4; j++){ acc[i][j][0]=0; acc[i][j][1]=0; acc[i][j][2]=0; acc[i][j][3]=0; }

    for (int t = 0; t < K1/32; t++){
        const int kt = t*32;
        #pragma unroll
        for (int i = 0; i < 4; i++){
            int idx = tid + i*256;
            int r = idx >> 3, c4 = (idx & 7)*4;
            int kg = kt + c4;
            const float* src;
            if (kg < HID)          src = g_xh + s_ii[r]*HID + kg;
            else if (kg < 2*HID)   src = g_xh + s_jj[r]*HID + (kg - HID);
            else                   src = weight + (size_t)(e0 + r)*EDIM + (kg - 2*HID);
            *(uint4*)&sA[r*PADK + c4] = cvt4(*(const float4*)src);
        }
        #pragma unroll
        for (int i = 0; i < 4; i++){
            int idx = tid + i*256;
            int r = idx >> 3, c4 = (idx & 7)*4;
            *(uint4*)&sB[r*PADK + c4] = cvt4(*(const float4*)(g_WeT1 + (size_t)r*K1 + kt + c4));
        }
        __syncthreads();
        #pragma unroll
        for (int k0 = 0; k0 < 32; k0 += 8){
            uint32_t a[4][4];
            #pragma unroll
            for (int mt = 0; mt < 4; mt++) LOAD_AFRAG(a[mt], sA, wm + mt*16, k0, lr, lc);
            #pragma unroll
            for (int nt = 0; nt < 4; nt++){
                int n = wn + nt*8 + lr;
                uint32_t b0 = sB[n*PADK + k0 + lc];
                uint32_t b1 = sB[n*PADK + k0 + 4 + lc];
                #pragma unroll
                for (int mt = 0; mt < 4; mt++) mma8(acc[mt][nt], a[mt], b0, b1);
            }
        }
        __syncthreads();
    }
    // epilogue
    #pragma unroll
    for (int mt = 0; mt < 4; mt++){
        int r1 = wm + mt*16 + lr;
        #pragma unroll
        for (int nt = 0; nt < 4; nt++){
            int c = wn + nt*8 + lc*2;
            float2 v1, v2;
            v1.x = silu_f(acc[mt][nt][0] + sBias[c]);
            v1.y = silu_f(acc[mt][nt][1] + sBias[c+1]);
            v2.x = silu_f(acc[mt][nt][2] + sBias[c]);
            v2.y = silu_f(acc[mt][nt][3] + sBias[c+1]);
            *(float2*)(g_m + (size_t)(e0 + r1)*HID + c) = v1;
            *(float2*)(g_m + (size_t)(e0 + r1 + 8)*HID + c) = v2;
        }
    }
}

// -------- edge MLP layer 2 + attention + gated message + segment-sum --------
__global__ void __launch_bounds__(256) edge_mlp2_mma(const float* __restrict__ be2,
                                                     const float* __restrict__ Wa,
                                                     const float* __restrict__ ba,
                                                     const int* __restrict__ ei){
    __shared__ uint32_t sA[128*PADK];
    __shared__ uint32_t sB[128*PADK];
    __shared__ float sBias[128], sWa[128], s_att[128];
    __shared__ int s_ii[128];
    const int tid = threadIdx.x;
    const int e0  = blockIdx.x*128;
    if (tid < 128){
        s_ii[tid] = ei[e0 + tid];
        sBias[tid] = be2[tid];
        sWa[tid] = Wa[tid];
    }
    __syncthreads();
    const int lane = tid & 31, lr = lane >> 2, lc = lane & 3;
    const int wid = tid >> 5;
    const int wm = (wid & 1)*64;
    const int wn = (wid >> 1)*32;
    float acc[4][4][4];
    #pragma unroll
    for (int i = 0; i < 4; i++)
        #pragma unroll
        for (int j = 0; j < 4; j++){ acc[i][j][0]=0; acc[i][j][1]=0; acc[i][j][2]=0; acc[i][j][3]=0; }

    for (int t = 0; t < 4; t++){
        const int kt = t*32;
        #pragma unroll
        for (int i = 0; i < 4; i++){
            int idx = tid + i*256;
            int r = idx >> 3, c4 = (idx & 7)*4;
            *(uint4*)&sA[r*PADK + c4] = cvt4(*(const float4*)(g_m + (size_t)(e0 + r)*HID + kt + c4));
        }
        #pragma unroll
        for (int i = 0; i < 4; i++){
            int idx = tid + i*256;
            int r = idx >> 3, c4 = (idx & 7)*4;
            *(uint4*)&sB[r*PADK + c4] = cvt4(*(const float4*)(g_We2T + (size_t)r*HID + kt + c4));
        }
        __syncthreads();
        #pragma unroll
        for (int k0 = 0; k0 < 32; k0 += 8){
            uint32_t a[4][4];
            #pragma unroll
            for (int mt = 0; mt < 4; mt++) LOAD_AFRAG(a[mt], sA, wm + mt*16, k0, lr, lc);
            #pragma unroll
            for (int nt = 0; nt < 4; nt++){
                int n = wn + nt*8 + lr;
                uint32_t b0 = sB[n*PADK + k0 + lc];
                uint32_t b1 = sB[n*PADK + k0 + 4 + lc];
                #pragma unroll
                for (int mt = 0; mt < 4; mt++) mma8(acc[mt][nt], a[mt], b0, b1);
            }
        }
        __syncthreads();
    }
    // m2 = silu(acc + bias); partial attention dots -> s_att
    if (tid < 128) s_att[tid] = 0.0f;
    __syncthreads();
    #pragma unroll
    for (int mt = 0; mt < 4; mt++){
        float p0 = 0.0f, p1 = 0.0f;
        #pragma unroll
        for (int nt = 0; nt < 4; nt++){
            int c = wn + nt*8 + lc*2;
            float wa0 = sWa[c], wa1 = sWa[c+1];
            float v0 = silu_f(acc[mt][nt][0] + sBias[c]);
            float v1 = silu_f(acc[mt][nt][1] + sBias[c+1]);
            float v2 = silu_f(acc[mt][nt][2] + sBias[c]);
            float v3 = silu_f(acc[mt][nt][3] + sBias[c+1]);
            acc[mt][nt][0]=v0; acc[mt][nt][1]=v1; acc[mt][nt][2]=v2; acc[mt][nt][3]=v3;
            p0 += v0*wa0 + v1*wa1;
            p1 += v2*wa0 + v3*wa1;
        }
        atomicAdd(&s_att[wm + mt*16 + lr], p0);
        atomicAdd(&s_att[wm + mt*16 + lr + 8], p1);
    }
    __syncthreads();
    const float ba0 = ba[0];
    #pragma unroll
    for (int mt = 0; mt < 4; mt++){
        int r1 = wm + mt*16 + lr, r2 = r1 + 8;
        float att1 = silu_f(s_att[r1] + ba0);
        float att2 = silu_f(s_att[r2] + ba0);
        int n1 = s_ii[r1], n2 = s_ii[r2];
        #pragma unroll
        for (int nt = 0; nt < 4; nt++){
            int c = wn + nt*8 + lc*2;
            float2 v1, v2;
            v1.x = acc[mt][nt][0]*att1; v1.y = acc[mt][nt][1]*att1;
            v2.x = acc[mt][nt][2]*att2; v2.y = acc[mt][nt][3]*att2;
            *(float2*)(g_m + (size_t)(e0 + r1)*HID + c) = v1;
            *(float2*)(g_m + (size_t)(e0 + r2)*HID + c) = v2;
            asm volatile("red.global.add.v2.f32 [%0], {%1,%2};"
                         :: "l"(g_agg + (size_t)n1*HID + c), "f"(v1.x), "f"(v1.y) : "memory");
            asm volatile("red.global.add.v2.f32 [%0], {%1,%2};"
                         :: "l"(g_agg + (size_t)n2*HID + c), "f"(v2.x), "f"(v2.y) : "memory");
        }
    }
    if (tid < 128) atomicAdd(&g_cnt[s_ii[tid]], 1.0f);
}

// -------- edge out: edgeh = weight + silu(m_ij @ Wo + bo); N tiled by gridDim.y --------
__global__ void __launch_bounds__(256) edge_out_mma(const float* __restrict__ bo,
                                                    const float* __restrict__ weight,
                                                    float* __restrict__ out){
    __shared__ uint32_t sA[128*PADK];
    __shared__ uint32_t sB[128*PADK];
    __shared__ float sBias[128];
    const int tid = threadIdx.x;
    const int e0  = blockIdx.x*128;
    const int nb  = blockIdx.y*128;
    if (tid < 128) sBias[tid] = (nb + tid < EDIM) ? bo[nb + tid] : 0.0f;
    __syncthreads();
    const int lane = tid & 31, lr = lane >> 2, lc = lane & 3;
    const int wid = tid >> 5;
    const int wm = (wid & 1)*64;
    const int wn = (wid >> 1)*32;
    float acc[4][4][4];
    #pragma unroll
    for (int i = 0; i < 4; i++)
        #pragma unroll
        for (int j = 0; j < 4; j++){ acc[i][j][0]=0; acc[i][j][1]=0; acc[i][j][2]=0; acc[i][j][3]=0; }

    for (int t = 0; t < 4; t++){
        const int kt = t*32;
        #pragma unroll
        for (int i = 0; i < 4; i++){
            int idx = tid + i*256;
            int r = idx >> 3, c4 = (idx & 7)*4;
            *(uint4*)&sA[r*PADK + c4] = cvt4(*(const float4*)(g_m + (size_t)(e0 + r)*HID + kt + c4));
        }
        #pragma unroll
        for (int i = 0; i < 4; i++){
            int idx = tid + i*256;
            int r = idx >> 3, c4 = (idx & 7)*4;
            *(uint4*)&sB[r*PADK + c4] = cvt4(*(const float4*)(g_WoT + (size_t)(nb + r)*HID + kt + c4));
        }
        __syncthreads();
        #pragma unroll
        for (int k0 = 0; k0 < 32; k0 += 8){
            uint32_t a[4][4];
            #pragma unroll
            for (int mt = 0; mt < 4; mt++) LOAD_AFRAG(a[mt], sA, wm + mt*16, k0, lr, lc);
            #pragma unroll
            for (int nt = 0; nt < 4; nt++){
                int n = wn + nt*8 + lr;
                uint32_t b0 = sB[n*PADK + k0 + lc];
                uint32_t b1 = sB[n*PADK + k0 + 4 + lc];
                #pragma unroll
                for (int mt = 0; mt < 4; mt++) mma8(acc[mt][nt], a[mt], b0, b1);
            }
        }
        __syncthreads();
    }
    #pragma unroll
    for (int mt = 0; mt < 4; mt++){
        int r1 = e0 + wm + mt*16 + lr;
        #pragma unroll
        for (int nt = 0; nt < 4; nt++){
            int c = wn + nt*8 + lc*2;
            int g = nb + c;
            if (g < EDIM){
                float2 w1 = *(const float2*)(weight + (size_t)r1*EDIM + g);
                float2 w2 = *(const float2*)(weight + (size_t)(r1+8)*EDIM + g);
                float2 v1, v2;
                v1.x = w1.x + silu_f(acc[mt][nt][0] + sBias[c]);
                v1.y = w1.y + silu_f(acc[mt][nt][1] + sBias[c+1]);
                v2.x = w2.x + silu_f(acc[mt][nt][2] + sBias[c]);
                v2.y = w2.y + silu_f(acc[mt][nt][3] + sBias[c+1]);
                *(float2*)(out + X_OUT_ELEMS + (size_t)r1*EDIM + g) = v1;
                *(float2*)(out + X_OUT_ELEMS + (size_t)(r1+8)*EDIM + g) = v2;
            }
        }
    }
}

// ================= scalar node kernels =================
__global__ void __launch_bounds__(256) node_mlp1_kernel(const float* __restrict__ Wn1,
                                                        const float* __restrict__ bn1){
    __shared__ float sA[64*33];
    __shared__ float sB[32*128];
    __shared__ float s_inv[64];
    const int tid = threadIdx.x;
    const int r0  = blockIdx.x*64;
    if (tid < 64){
        int node = min(r0 + tid, N_NODES - 1);
        float c = g_cnt[node];
        s_inv[tid] = 1.0f / ((c == 0.0f) ? 1.0f : c);
    }
    __syncthreads();
    const int m0 = (tid >> 5)*8;
    const int n0 = (tid & 31)*4;
    float acc[8][4];
    #pragma unroll
    for (int i = 0; i < 8; i++){ acc[i][0]=0; acc[i][1]=0; acc[i][2]=0; acc[i][3]=0; }

    for (int kt = 0; kt < 2*HID; kt += 32){
        #pragma unroll
        for (int i = 0; i < 8; i++){
            int idx = tid + i*256;
            int r = idx >> 5, k = idx & 31;
            int kg = kt + k;
            int node = min(r0 + r, N_NODES - 1);
            float v = (kg < HID) ? g_xh[node*HID + kg]
                                 : g_agg[node*HID + (kg - HID)] * s_inv[r];
            sA[r*33 + k] = v;
        }
        #pragma unroll
        for (int i = 0; i < 16; i++){
            int idx = tid + i*256;
            int k = idx >> 7, n = idx & 127;
            sB[k*128 + n] = Wn1[(kt + k)*128 + n];
        }
        __syncthreads();
        #pragma unroll
        for (int kk = 0; kk < 32; kk++){
            float4 bv = *(const float4*)&sB[kk*128 + n0];
            #pragma unroll
            for (int i = 0; i < 8; i++){
                float a = sA[(m0+i)*33 + kk];
                acc[i][0] += a*bv.x; acc[i][1] += a*bv.y;
                acc[i][2] += a*bv.z; acc[i][3] += a*bv.w;
            }
        }
        __syncthreads();
    }
    float4 bias = *(const float4*)&bn1[n0];
    #pragma unroll
    for (int i = 0; i < 8; i++){
        int row = r0 + m0 + i;
        if (row < N_NODES){
            float4 o;
            o.x = silu_f(acc[i][0] + bias.x);
            o.y = silu_f(acc[i][1] + bias.y);
            o.z = silu_f(acc[i][2] + bias.z);
            o.w = silu_f(acc[i][3] + bias.w);
            *(float4*)&g_n1[row*HID + n0] = o;
        }
    }
}

__global__ void __launch_bounds__(256) node_mlp2_kernel(const float* __restrict__ Wn2,
                                                        const float* __restrict__ bn2,
                                                        float* __restrict__ out){
    __shared__ float sA[64*33];
    __shared__ float sB[32*128];
    const int tid = threadIdx.x;
    const int r0  = blockIdx.x*64;
    const int m0 = (tid >> 5)*8;
    const int n0 = (tid & 31)*4;
    float acc[8][4];
    #pragma unroll
    for (int i = 0; i < 8; i++){ acc[i][0]=0; acc[i][1]=0; acc[i][2]=0; acc[i][3]=0; }

    for (int kt = 0; kt < HID; kt += 32){
        #pragma unroll
        for (int i = 0; i < 8; i++){
            int idx = tid + i*256;
            int r = idx >> 5, k = idx & 31;
            int node = min(r0 + r, N_NODES - 1);
            sA[r*33 + k] = g_n1[node*HID + kt + k];
        }
        #pragma unroll
        for (int i = 0; i < 16; i++){
            int idx = tid + i*256;
            int k = idx >> 7, n = idx & 127;
            sB[k*128 + n] = Wn2[(kt + k)*128 + n];
        }
        __syncthreads();
        #pragma unroll
        for (int kk = 0; kk < 32; kk++){
            float4 bv = *(const float4*)&sB[kk*128 + n0];
            #pragma unroll
            for (int i = 0; i < 8; i++){
                float a = sA[(m0+i)*33 + kk];
                acc[i][0] += a*bv.x; acc[i][1] += a*bv.y;
                acc[i][2] += a*bv.z; acc[i][3] += a*bv.w;
            }
        }
        __syncthreads();
    }
    float4 bias = *(const float4*)&bn2[n0];
    #pragma unroll
    for (int i = 0; i < 8; i++){
        int row = r0 + m0 + i;
        if (row < N_NODES){
            float4 xh4 = *(const float4*)&g_xh[row*HID + n0];
            float4 o;
            o.x = xh4.x + silu_f(acc[i][0] + bias.x);
            o.y = xh4.y + silu_f(acc[i][1] + bias.y);
            o.z = xh4.z + silu_f(acc[i][2] + bias.z);
            o.w = xh4.w + silu_f(acc[i][3] + bias.w);
            *(float4*)&out[row*HID + n0] = o;
        }
    }
}

extern "C" void kernel_launch(void* const* d_in, const int* in_sizes, int n_in,
                              void* d_out, int out_size){
    const float* x    = (const float*)d_in[0];
    const float* wgt  = (const float*)d_in[1];
    const float* ln_g = (const float*)d_in[2];
    const float* ln_b = (const float*)d_in[3];
    const float* We1  = (const float*)d_in[4];
    const float* be1  = (const float*)d_in[5];
    const float* We2  = (const float*)d_in[6];
    const float* be2  = (const float*)d_in[7];
    const float* Wa   = (const float*)d_in[8];
    const float* ba   = (const float*)d_in[9];
    const float* Wn1  = (const float*)d_in[10];
    const float* bn1  = (const float*)d_in[11];
    const float* Wn2  = (const float*)d_in[12];
    const float* bn2  = (const float*)d_in[13];
    const float* Wo   = (const float*)d_in[14];
    const float* bo   = (const float*)d_in[15];
    const int*   ei   = (const int*)d_in[16];
    float* out = (float*)d_out;

    zero_kernel<<<(N_NODES*HID + 255)/256, 256>>>();
    tr_we1<<<(128*672 + 255)/256, 256>>>(We1);
    tr_we2<<<(128*128 + 255)/256, 256>>>(We2);
    tr_wo <<<(512*128 + 255)/256, 256>>>(Wo);
    ln_kernel<<<(N_NODES + 7)/8, dim3(32, 8)>>>(x, ln_g, ln_b);
    edge_mlp1_mma<<<N_EDGES/128, 256>>>(be1, wgt, ei);
    edge_mlp2_mma<<<N_EDGES/128, 256>>>(be2, Wa, ba, ei);
    node_mlp1_kernel<<<(N_NODES + 63)/64, 256>>>(Wn1, bn1);
    node_mlp2_kernel<<<(N_NODES + 63)/64, 256>>>(Wn2, bn2, out);
    edge_out_mma<<<dim3(N_EDGES/128, 4), 256>>>(bo, wgt, out);
}

// round 5
// speedup vs baseline: 4.3239x; 1.4103x over previous
#include <cuda_runtime.h>
#include <math.h>
#include <stdint.h>

#define N_NODES 10000
#define HID 128
#define EDIM 416
#define N_EDGES 160000
#define K1 (2*HID+EDIM)              // 672
#define X_OUT_ELEMS (N_NODES*HID)    // 1,280,000

// -------- scratch (device globals; no allocations allowed) --------
__device__ __align__(128) float    g_xh[N_NODES*HID];
__device__ __align__(128) uint32_t g_m[N_EDGES*HID];   // tf32 bit patterns (m1, then m_ij)
__device__ __align__(128) float    g_agg[N_NODES*HID];
__device__ __align__(128) float    g_cnt[N_NODES];
__device__ __align__(128) float    g_n1[N_NODES*HID];
// pre-transposed + tf32-converted weights: WT[n][k]
__device__ __align__(128) uint32_t g_WeT1[128*672];
__device__ __align__(128) uint32_t g_We2T[128*128];
__device__ __align__(128) uint32_t g_WoT[512*128];     // rows 416..511 zero

__device__ __forceinline__ float silu_f(float x){ return x / (1.0f + __expf(-x)); }
__device__ __forceinline__ uint32_t tf32b(float x){
    uint32_t y; asm("cvt.rna.tf32.f32 %0, %1;" : "=r"(y) : "f"(x)); return y;
}
__device__ __forceinline__ uint32_t smem_u32(const void* p){
    uint32_t a;
    asm("{ .reg .u64 t; cvta.to.shared.u64 t, %1; cvt.u32.u64 %0, t; }" : "=r"(a) : "l"(p));
    return a;
}
__device__ __forceinline__ void mma8(float* c, const uint32_t* a, uint32_t b0, uint32_t b1){
    asm volatile("mma.sync.aligned.m16n8k8.row.col.f32.tf32.tf32.f32 "
        "{%0,%1,%2,%3}, {%4,%5,%6,%7}, {%8,%9}, {%0,%1,%2,%3};"
        : "+f"(c[0]), "+f"(c[1]), "+f"(c[2]), "+f"(c[3])
        : "r"(a[0]), "r"(a[1]), "r"(a[2]), "r"(a[3]), "r"(b0), "r"(b1));
}

#define CP_ASYNC16(dst, src) \
    asm volatile("cp.async.cg.shared.global [%0], [%1], 16;" :: "r"(dst), "l"(src) : "memory")
#define CP_COMMIT() asm volatile("cp.async.commit_group;" ::: "memory")
#define CP_WAIT(n)  asm volatile("cp.async.wait_group %0;" :: "n"(n) : "memory")

// swizzled word index inside a 128-row x 32-word tile (rows 128B, 16B chunks XOR'd by row)
__device__ __forceinline__ int swzi(int r, int k){
    return r*32 + ((((k >> 2) ^ r) & 7) << 2) + (k & 3);
}
// stage layout in dynamic smem (uint32 words): A0[4096] A1[4096] B0[4096] B1[4096]
#define STAGE_WORDS 4096
#define SMEM_BYTES  (4*STAGE_WORDS*4)

// ================= setup: zero agg/cnt + transpose/convert weights =================
__global__ void setup_kernel(const float* __restrict__ We1, const float* __restrict__ We2,
                             const float* __restrict__ Wo){
    int i = blockIdx.x*blockDim.x + threadIdx.x;
    if (i < N_NODES*HID) g_agg[i] = 0.0f;
    if (i < N_NODES)     g_cnt[i] = 0.0f;
    if (i < 128*672){ int n = i/672, k = i%672; g_WeT1[i] = tf32b(We1[k*128 + n]); }
    if (i < 128*128){ int n = i/128, k = i%128; g_We2T[i] = tf32b(We2[k*128 + n]); }
    if (i < 512*128){ int n = i/128, k = i%128; g_WoT[i] = (n < EDIM) ? tf32b(Wo[k*EDIM + n]) : 0u; }
}

// -------- layernorm --------
__global__ void ln_kernel(const float* __restrict__ x,
                          const float* __restrict__ g,
                          const float* __restrict__ b){
    int row = blockIdx.x*8 + threadIdx.y;
    if (row >= N_NODES) return;
    int lane = threadIdx.x;
    float4 v = ((const float4*)(x + row*HID))[lane];
    float s = v.x + v.y + v.z + v.w;
    #pragma unroll
    for (int o = 16; o > 0; o >>= 1) s += __shfl_xor_sync(0xffffffffu, s, o);
    float mu = s * (1.0f/HID);
    float dx = v.x-mu, dy = v.y-mu, dz = v.z-mu, dw = v.w-mu;
    float q = dx*dx + dy*dy + dz*dz + dw*dw;
    #pragma unroll
    for (int o = 16; o > 0; o >>= 1) q += __shfl_xor_sync(0xffffffffu, q, o);
    float rstd = rsqrtf(q*(1.0f/HID) + 1e-5f);
    float4 gg = ((const float4*)g)[lane];
    float4 bb = ((const float4*)b)[lane];
    float4 o4;
    o4.x = dx*rstd*gg.x + bb.x;
    o4.y = dy*rstd*gg.y + bb.y;
    o4.z = dz*rstd*gg.z + bb.z;
    o4.w = dw*rstd*gg.w + bb.w;
    ((float4*)(g_xh + row*HID))[lane] = o4;
}

// ============ pipelined MMA edge kernels: 128x128 tile, 8 warps (2x4), warp tile 64x32 ============

// MMA on one staged tile. A fragments optionally tf32-converted (CVTA).
#define MMA_TILE(tA, tB, CVTA) do { \
    _Pragma("unroll") \
    for (int k0 = 0; k0 < 32; k0 += 8){ \
        uint32_t a[4][4]; \
        _Pragma("unroll") \
        for (int mt = 0; mt < 4; mt++){ \
            int R0 = wm + mt*16 + lr; \
            a[mt][0] = CVTA((tA)[swzi(R0,     k0 + lc)]); \
            a[mt][1] = CVTA((tA)[swzi(R0 + 8, k0 + lc)]); \
            a[mt][2] = CVTA((tA)[swzi(R0,     k0 + 4 + lc)]); \
            a[mt][3] = CVTA((tA)[swzi(R0 + 8, k0 + 4 + lc)]); \
        } \
        _Pragma("unroll") \
        for (int nt = 0; nt < 4; nt++){ \
            int n = wn + nt*8 + lr; \
            uint32_t b0 = (tB)[swzi(n, k0 + lc)]; \
            uint32_t b1 = (tB)[swzi(n, k0 + 4 + lc)]; \
            _Pragma("unroll") \
            for (int mt = 0; mt < 4; mt++) mma8(acc[mt][nt], a[mt], b0, b1); \
        } \
    } \
} while(0)

#define CVT_TF32(u) tf32b(__uint_as_float(u))
#define CVT_NONE(u) (u)

// -------- edge MLP layer 1: m1 = silu([xh_i|xh_j|w] @ We1 + be1) -> g_m (tf32 bits) --------
__global__ void __launch_bounds__(256, 2) edge_mlp1_mma(const float* __restrict__ be1,
                                                        const float* __restrict__ weight,
                                                        const int* __restrict__ ei){
    extern __shared__ uint32_t dynsm[];
    __shared__ float sBias[128];
    __shared__ int s_ii[128], s_jj[128];
    const int tid = threadIdx.x;
    const int e0  = blockIdx.x*128;
    if (tid < 128){
        s_ii[tid] = ei[e0 + tid];
        s_jj[tid] = ei[N_EDGES + e0 + tid];
        sBias[tid] = be1[tid];
    }
    __syncthreads();
    const uint32_t sbase = smem_u32(dynsm);
    const int lane = tid & 31, lr = lane >> 2, lc = lane & 3;
    const int wid = tid >> 5;
    const int wm = (wid & 1)*64, wn = (wid >> 1)*32;
    float acc[4][4][4];
    #pragma unroll
    for (int i = 0; i < 4; i++)
        #pragma unroll
        for (int j = 0; j < 4; j++){ acc[i][j][0]=0; acc[i][j][1]=0; acc[i][j][2]=0; acc[i][j][3]=0; }

    const int lr8 = tid >> 3, lc8 = tid & 7;   // loader: 4 chunk-pairs per thread

    #define ISSUE1(st, kt) do { \
        uint32_t ab = sbase + (st)*(STAGE_WORDS*4); \
        uint32_t bb = sbase + 2*(STAGE_WORDS*4) + (st)*(STAGE_WORDS*4); \
        _Pragma("unroll") \
        for (int i = 0; i < 4; i++){ \
            int r = lr8 + i*32, c = lc8; \
            int kg = (kt) + c*4; \
            const void* srcA; \
            if (kg < HID)        srcA = g_xh + s_ii[r]*HID + kg; \
            else if (kg < 2*HID) srcA = g_xh + s_jj[r]*HID + (kg - HID); \
            else                 srcA = weight + (size_t)(e0 + r)*EDIM + (kg - 2*HID); \
            uint32_t off = (uint32_t)(r*32 + (((c ^ r) & 7) << 2))*4u; \
            CP_ASYNC16(ab + off, srcA); \
            CP_ASYNC16(bb + off, (const void*)(g_WeT1 + (size_t)r*K1 + kg)); \
        } \
        CP_COMMIT(); \
    } while(0)

    ISSUE1(0, 0);
    for (int t = 0; t < K1/32; t++){
        if (t + 1 < K1/32){ ISSUE1((t+1)&1, (t+1)*32); CP_WAIT(1); }
        else CP_WAIT(0);
        __syncthreads();
        const uint32_t* tA = dynsm + (t&1)*STAGE_WORDS;
        const uint32_t* tB = dynsm + 2*STAGE_WORDS + (t&1)*STAGE_WORDS;
        MMA_TILE(tA, tB, CVT_TF32);
        __syncthreads();
    }
    #undef ISSUE1
    // epilogue: silu + bias -> tf32 bits
    #pragma unroll
    for (int mt = 0; mt < 4; mt++){
        int r1 = wm + mt*16 + lr;
        #pragma unroll
        for (int nt = 0; nt < 4; nt++){
            int c = wn + nt*8 + lc*2;
            uint2 v1, v2;
            v1.x = tf32b(silu_f(acc[mt][nt][0] + sBias[c]));
            v1.y = tf32b(silu_f(acc[mt][nt][1] + sBias[c+1]));
            v2.x = tf32b(silu_f(acc[mt][nt][2] + sBias[c]));
            v2.y = tf32b(silu_f(acc[mt][nt][3] + sBias[c+1]));
            *(uint2*)(g_m + (size_t)(e0 + r1)*HID + c) = v1;
            *(uint2*)(g_m + (size_t)(e0 + r1 + 8)*HID + c) = v2;
        }
    }
}

// -------- edge MLP layer 2 + attention + gated message + segment-sum --------
__global__ void __launch_bounds__(256, 2) edge_mlp2_mma(const float* __restrict__ be2,
                                                        const float* __restrict__ Wa,
                                                        const float* __restrict__ ba,
                                                        const int* __restrict__ ei){
    extern __shared__ uint32_t dynsm[];
    __shared__ float sBias[128], sWa[128], s_att[128];
    __shared__ int s_ii[128];
    const int tid = threadIdx.x;
    const int e0  = blockIdx.x*128;
    if (tid < 128){
        s_ii[tid] = ei[e0 + tid];
        sBias[tid] = be2[tid];
        sWa[tid] = Wa[tid];
        s_att[tid] = 0.0f;
    }
    __syncthreads();
    const uint32_t sbase = smem_u32(dynsm);
    const int lane = tid & 31, lr = lane >> 2, lc = lane & 3;
    const int wid = tid >> 5;
    const int wm = (wid & 1)*64, wn = (wid >> 1)*32;
    float acc[4][4][4];
    #pragma unroll
    for (int i = 0; i < 4; i++)
        #pragma unroll
        for (int j = 0; j < 4; j++){ acc[i][j][0]=0; acc[i][j][1]=0; acc[i][j][2]=0; acc[i][j][3]=0; }

    const int lr8 = tid >> 3, lc8 = tid & 7;

    #define ISSUE2(st, kt) do { \
        uint32_t ab = sbase + (st)*(STAGE_WORDS*4); \
        uint32_t bb = sbase + 2*(STAGE_WORDS*4) + (st)*(STAGE_WORDS*4); \
        _Pragma("unroll") \
        for (int i = 0; i < 4; i++){ \
            int r = lr8 + i*32, c = lc8; \
            int kg = (kt) + c*4; \
            uint32_t off = (uint32_t)(r*32 + (((c ^ r) & 7) << 2))*4u; \
            CP_ASYNC16(ab + off, (const void*)(g_m + (size_t)(e0 + r)*HID + kg)); \
            CP_ASYNC16(bb + off, (const void*)(g_We2T + (size_t)r*HID + kg)); \
        } \
        CP_COMMIT(); \
    } while(0)

    ISSUE2(0, 0);
    for (int t = 0; t < 4; t++){
        if (t + 1 < 4){ ISSUE2((t+1)&1, (t+1)*32); CP_WAIT(1); }
        else CP_WAIT(0);
        __syncthreads();
        const uint32_t* tA = dynsm + (t&1)*STAGE_WORDS;
        const uint32_t* tB = dynsm + 2*STAGE_WORDS + (t&1)*STAGE_WORDS;
        MMA_TILE(tA, tB, CVT_NONE);
        __syncthreads();
    }
    #undef ISSUE2
    // m2 = silu(acc + bias); attention partial dots
    #pragma unroll
    for (int mt = 0; mt < 4; mt++){
        float p0 = 0.0f, p1 = 0.0f;
        #pragma unroll
        for (int nt = 0; nt < 4; nt++){
            int c = wn + nt*8 + lc*2;
            float wa0 = sWa[c], wa1 = sWa[c+1];
            float v0 = silu_f(acc[mt][nt][0] + sBias[c]);
            float v1 = silu_f(acc[mt][nt][1] + sBias[c+1]);
            float v2 = silu_f(acc[mt][nt][2] + sBias[c]);
            float v3 = silu_f(acc[mt][nt][3] + sBias[c+1]);
            acc[mt][nt][0]=v0; acc[mt][nt][1]=v1; acc[mt][nt][2]=v2; acc[mt][nt][3]=v3;
            p0 += v0*wa0 + v1*wa1;
            p1 += v2*wa0 + v3*wa1;
        }
        atomicAdd(&s_att[wm + mt*16 + lr], p0);
        atomicAdd(&s_att[wm + mt*16 + lr + 8], p1);
    }
    __syncthreads();
    const float ba0 = ba[0];
    #pragma unroll
    for (int mt = 0; mt < 4; mt++){
        int r1 = wm + mt*16 + lr, r2 = r1 + 8;
        float att1 = silu_f(s_att[r1] + ba0);
        float att2 = silu_f(s_att[r2] + ba0);
        int n1 = s_ii[r1], n2 = s_ii[r2];
        #pragma unroll
        for (int nt = 0; nt < 4; nt++){
            int c = wn + nt*8 + lc*2;
            float2 v1, v2;
            v1.x = acc[mt][nt][0]*att1; v1.y = acc[mt][nt][1]*att1;
            v2.x = acc[mt][nt][2]*att2; v2.y = acc[mt][nt][3]*att2;
            uint2 u1, u2;
            u1.x = tf32b(v1.x); u1.y = tf32b(v1.y);
            u2.x = tf32b(v2.x); u2.y = tf32b(v2.y);
            *(uint2*)(g_m + (size_t)(e0 + r1)*HID + c) = u1;
            *(uint2*)(g_m + (size_t)(e0 + r2)*HID + c) = u2;
            asm volatile("red.global.add.v2.f32 [%0], {%1,%2};"
                         :: "l"(g_agg + (size_t)n1*HID + c), "f"(v1.x), "f"(v1.y) : "memory");
            asm volatile("red.global.add.v2.f32 [%0], {%1,%2};"
                         :: "l"(g_agg + (size_t)n2*HID + c), "f"(v2.x), "f"(v2.y) : "memory");
        }
    }
    if (tid < 128) atomicAdd(&g_cnt[s_ii[tid]], 1.0f);
}

// -------- edge out: edgeh = weight + silu(m_ij @ Wo + bo); N tiled by gridDim.y --------
__global__ void __launch_bounds__(256, 2) edge_out_mma(const float* __restrict__ bo,
                                                       const float* __restrict__ weight,
                                                       float* __restrict__ out){
    extern __shared__ uint32_t dynsm[];
    __shared__ float sBias[128];
    const int tid = threadIdx.x;
    const int e0  = blockIdx.x*128;
    const int nb  = blockIdx.y*128;
    if (tid < 128) sBias[tid] = (nb + tid < EDIM) ? bo[nb + tid] : 0.0f;
    __syncthreads();
    const uint32_t sbase = smem_u32(dynsm);
    const int lane = tid & 31, lr = lane >> 2, lc = lane & 3;
    const int wid = tid >> 5;
    const int wm = (wid & 1)*64, wn = (wid >> 1)*32;
    float acc[4][4][4];
    #pragma unroll
    for (int i = 0; i < 4; i++)
        #pragma unroll
        for (int j = 0; j < 4; j++){ acc[i][j][0]=0; acc[i][j][1]=0; acc[i][j][2]=0; acc[i][j][3]=0; }

    const int lr8 = tid >> 3, lc8 = tid & 7;

    #define ISSUE3(st, kt) do { \
        uint32_t ab = sbase + (st)*(STAGE_WORDS*4); \
        uint32_t bb = sbase + 2*(STAGE_WORDS*4) + (st)*(STAGE_WORDS*4); \
        _Pragma("unroll") \
        for (int i = 0; i < 4; i++){ \
            int r = lr8 + i*32, c = lc8; \
            int kg = (kt) + c*4; \
            uint32_t off = (uint32_t)(r*32 + (((c ^ r) & 7) << 2))*4u; \
            CP_ASYNC16(ab + off, (const void*)(g_m + (size_t)(e0 + r)*HID + kg)); \
            CP_ASYNC16(bb + off, (const void*)(g_WoT + (size_t)(nb + r)*HID + kg)); \
        } \
        CP_COMMIT(); \
    } while(0)

    ISSUE3(0, 0);
    for (int t = 0; t < 4; t++){
        if (t + 1 < 4){ ISSUE3((t+1)&1, (t+1)*32); CP_WAIT(1); }
        else CP_WAIT(0);
        __syncthreads();
        const uint32_t* tA = dynsm + (t&1)*STAGE_WORDS;
        const uint32_t* tB = dynsm + 2*STAGE_WORDS + (t&1)*STAGE_WORDS;
        MMA_TILE(tA, tB, CVT_NONE);
        __syncthreads();
    }
    #undef ISSUE3
    #pragma unroll
    for (int mt = 0; mt < 4; mt++){
        int r1 = e0 + wm + mt*16 + lr;
        #pragma unroll
        for (int nt = 0; nt < 4; nt++){
            int c = wn + nt*8 + lc*2;
            int g = nb + c;
            if (g < EDIM){
                float2 w1 = *(const float2*)(weight + (size_t)r1*EDIM + g);
                float2 w2 = *(const float2*)(weight + (size_t)(r1+8)*EDIM + g);
                float2 v1, v2;
                v1.x = w1.x + silu_f(acc[mt][nt][0] + sBias[c]);
                v1.y = w1.y + silu_f(acc[mt][nt][1] + sBias[c+1]);
                v2.x = w2.x + silu_f(acc[mt][nt][2] + sBias[c]);
                v2.y = w2.y + silu_f(acc[mt][nt][3] + sBias[c+1]);
                *(float2*)(out + X_OUT_ELEMS + (size_t)r1*EDIM + g) = v1;
                *(float2*)(out + X_OUT_ELEMS + (size_t)(r1+8)*EDIM + g) = v2;
            }
        }
    }
}

// ================= scalar node kernels =================
__global__ void __launch_bounds__(256) node_mlp1_kernel(const float* __restrict__ Wn1,
                                                        const float* __restrict__ bn1){
    __shared__ float sA[64*33];
    __shared__ float sB[32*128];
    __shared__ float s_inv[64];
    const int tid = threadIdx.x;
    const int r0  = blockIdx.x*64;
    if (tid < 64){
        int node = min(r0 + tid, N_NODES - 1);
        float c = g_cnt[node];
        s_inv[tid] = 1.0f / ((c == 0.0f) ? 1.0f : c);
    }
    __syncthreads();
    const int m0 = (tid >> 5)*8;
    const int n0 = (tid & 31)*4;
    float acc[8][4];
    #pragma unroll
    for (int i = 0; i < 8; i++){ acc[i][0]=0; acc[i][1]=0; acc[i][2]=0; acc[i][3]=0; }

    for (int kt = 0; kt < 2*HID; kt += 32){
        #pragma unroll
        for (int i = 0; i < 8; i++){
            int idx = tid + i*256;
            int r = idx >> 5, k = idx & 31;
            int kg = kt + k;
            int node = min(r0 + r, N_NODES - 1);
            float v = (kg < HID) ? g_xh[node*HID + kg]
                                 : g_agg[node*HID + (kg - HID)] * s_inv[r];
            sA[r*33 + k] = v;
        }
        #pragma unroll
        for (int i = 0; i < 16; i++){
            int idx = tid + i*256;
            int k = idx >> 7, n = idx & 127;
            sB[k*128 + n] = Wn1[(kt + k)*128 + n];
        }
        __syncthreads();
        #pragma unroll
        for (int kk = 0; kk < 32; kk++){
            float4 bv = *(const float4*)&sB[kk*128 + n0];
            #pragma unroll
            for (int i = 0; i < 8; i++){
                float a = sA[(m0+i)*33 + kk];
                acc[i][0] += a*bv.x; acc[i][1] += a*bv.y;
                acc[i][2] += a*bv.z; acc[i][3] += a*bv.w;
            }
        }
        __syncthreads();
    }
    float4 bias = *(const float4*)&bn1[n0];
    #pragma unroll
    for (int i = 0; i < 8; i++){
        int row = r0 + m0 + i;
        if (row < N_NODES){
            float4 o;
            o.x = silu_f(acc[i][0] + bias.x);
            o.y = silu_f(acc[i][1] + bias.y);
            o.z = silu_f(acc[i][2] + bias.z);
            o.w = silu_f(acc[i][3] + bias.w);
            *(float4*)&g_n1[row*HID + n0] = o;
        }
    }
}

__global__ void __launch_bounds__(256) node_mlp2_kernel(const float* __restrict__ Wn2,
                                                        const float* __restrict__ bn2,
                                                        float* __restrict__ out){
    __shared__ float sA[64*33];
    __shared__ float sB[32*128];
    const int tid = threadIdx.x;
    const int r0  = blockIdx.x*64;
    const int m0 = (tid >> 5)*8;
    const int n0 = (tid & 31)*4;
    float acc[8][4];
    #pragma unroll
    for (int i = 0; i < 8; i++){ acc[i][0]=0; acc[i][1]=0; acc[i][2]=0; acc[i][3]=0; }

    for (int kt = 0; kt < HID; kt += 32){
        #pragma unroll
        for (int i = 0; i < 8; i++){
            int idx = tid + i*256;
            int r = idx >> 5, k = idx & 31;
            int node = min(r0 + r, N_NODES - 1);
            sA[r*33 + k] = g_n1[node*HID + kt + k];
        }
        #pragma unroll
        for (int i = 0; i < 16; i++){
            int idx = tid + i*256;
            int k = idx >> 7, n = idx & 127;
            sB[k*128 + n] = Wn2[(kt + k)*128 + n];
        }
        __syncthreads();
        #pragma unroll
        for (int kk = 0; kk < 32; kk++){
            float4 bv = *(const float4*)&sB[kk*128 + n0];
            #pragma unroll
            for (int i = 0; i < 8; i++){
                float a = sA[(m0+i)*33 + kk];
                acc[i][0] += a*bv.x; acc[i][1] += a*bv.y;
                acc[i][2] += a*bv.z; acc[i][3] += a*bv.w;
            }
        }
        __syncthreads();
    }
    float4 bias = *(const float4*)&bn2[n0];
    #pragma unroll
    for (int i = 0; i < 8; i++){
        int row = r0 + m0 + i;
        if (row < N_NODES){
            float4 xh4 = *(const float4*)&g_xh[row*HID + n0];
            float4 o;
            o.x = xh4.x + silu_f(acc[i][0] + bias.x);
            o.y = xh4.y + silu_f(acc[i][1] + bias.y);
            o.z = xh4.z + silu_f(acc[i][2] + bias.z);
            o.w = xh4.w + silu_f(acc[i][3] + bias.w);
            *(float4*)&out[row*HID + n0] = o;
        }
    }
}

extern "C" void kernel_launch(void* const* d_in, const int* in_sizes, int n_in,
                              void* d_out, int out_size){
    const float* x    = (const float*)d_in[0];
    const float* wgt  = (const float*)d_in[1];
    const float* ln_g = (const float*)d_in[2];
    const float* ln_b = (const float*)d_in[3];
    const float* We1  = (const float*)d_in[4];
    const float* be1  = (const float*)d_in[5];
    const float* We2  = (const float*)d_in[6];
    const float* be2  = (const float*)d_in[7];
    const float* Wa   = (const float*)d_in[8];
    const float* ba   = (const float*)d_in[9];
    const float* Wn1  = (const float*)d_in[10];
    const float* bn1  = (const float*)d_in[11];
    const float* Wn2  = (const float*)d_in[12];
    const float* bn2  = (const float*)d_in[13];
    const float* Wo   = (const float*)d_in[14];
    const float* bo   = (const float*)d_in[15];
    const int*   ei   = (const int*)d_in[16];
    float* out = (float*)d_out;

    cudaFuncSetAttribute(edge_mlp1_mma, cudaFuncAttributeMaxDynamicSharedMemorySize, SMEM_BYTES);
    cudaFuncSetAttribute(edge_mlp2_mma, cudaFuncAttributeMaxDynamicSharedMemorySize, SMEM_BYTES);
    cudaFuncSetAttribute(edge_out_mma,  cudaFuncAttributeMaxDynamicSharedMemorySize, SMEM_BYTES);

    setup_kernel<<<(N_NODES*HID + 255)/256, 256>>>(We1, We2, Wo);
    ln_kernel<<<(N_NODES + 7)/8, dim3(32, 8)>>>(x, ln_g, ln_b);
    edge_mlp1_mma<<<N_EDGES/128, 256, SMEM_BYTES>>>(be1, wgt, ei);
    edge_mlp2_mma<<<N_EDGES/128, 256, SMEM_BYTES>>>(be2, Wa, ba, ei);
    node_mlp1_kernel<<<(N_NODES + 63)/64, 256>>>(Wn1, bn1);
    node_mlp2_kernel<<<(N_NODES + 63)/64, 256>>>(Wn2, bn2, out);
    edge_out_mma<<<dim3(N_EDGES/128, 4), 256, SMEM_BYTES>>>(bo, wgt, out);
}

// round 6
// speedup vs baseline: 4.4647x; 1.0326x over previous
#include <cuda_runtime.h>
#include <math.h>
#include <stdint.h>

#define N_NODES 10000
#define HID 128
#define EDIM 416
#define N_EDGES 160000
#define K1 (2*HID+EDIM)              // 672
#define X_OUT_ELEMS (N_NODES*HID)    // 1,280,000

// -------- scratch (device globals; no allocations allowed) --------
__device__ __align__(128) float g_xh[N_NODES*HID];
__device__ __align__(128) float g_m[N_EDGES*HID];     // m1, then m_ij (in place)
__device__ __align__(128) float g_agg[N_NODES*HID];
__device__ __align__(128) float g_cnt[N_NODES];
__device__ __align__(128) float g_n1[N_NODES*HID];
// pre-transposed weights: WT[n][k]
__device__ __align__(128) float g_WeT1[128*672];
__device__ __align__(128) float g_We2T[128*128];
__device__ __align__(128) float g_WoT[512*128];       // rows 416..511 zero

__device__ __forceinline__ float silu_f(float x){ return x / (1.0f + __expf(-x)); }
__device__ __forceinline__ uint32_t smem_u32(const void* p){
    uint32_t a;
    asm("{ .reg .u64 t; cvta.to.shared.u64 t, %1; cvt.u32.u64 %0, t; }" : "=r"(a) : "l"(p));
    return a;
}
// tf32 MMA on raw fp32 bit patterns (HW reads high 19 bits; truncation vs RNA is fine here)
__device__ __forceinline__ void mma8(float* c, const uint32_t* a, uint32_t b0, uint32_t b1){
    asm volatile("mma.sync.aligned.m16n8k8.row.col.f32.tf32.tf32.f32 "
        "{%0,%1,%2,%3}, {%4,%5,%6,%7}, {%8,%9}, {%0,%1,%2,%3};"
        : "+f"(c[0]), "+f"(c[1]), "+f"(c[2]), "+f"(c[3])
        : "r"(a[0]), "r"(a[1]), "r"(a[2]), "r"(a[3]), "r"(b0), "r"(b1));
}

#define CP_ASYNC16(dst, src) \
    asm volatile("cp.async.cg.shared.global [%0], [%1], 16;" :: "r"(dst), "l"(src) : "memory")
#define CP_COMMIT() asm volatile("cp.async.commit_group;" ::: "memory")
#define CP_WAIT(n)  asm volatile("cp.async.wait_group %0;" :: "n"(n) : "memory")

// swizzled word index inside a 128-row x 32-word tile (rows 128B, 16B chunks XOR'd by row)
__device__ __forceinline__ int swzi(int r, int k){
    return r*32 + ((((k >> 2) ^ r) & 7) << 2) + (k & 3);
}
// 3-stage dynamic smem: A0 A1 A2 B0 B1 B2, each 4096 words (16KB)
#define STAGE_WORDS 4096
#define NSTAGE 3
#define SMEM_BYTES  (2*NSTAGE*STAGE_WORDS*4)   // 96KB

// ================= setup: zero agg/cnt + transpose weights =================
__global__ void setup_kernel(const float* __restrict__ We1, const float* __restrict__ We2,
                             const float* __restrict__ Wo){
    int i = blockIdx.x*blockDim.x + threadIdx.x;
    if (i < N_NODES*HID) g_agg[i] = 0.0f;
    if (i < N_NODES)     g_cnt[i] = 0.0f;
    if (i < 128*672){ int n = i/672, k = i%672; g_WeT1[i] = We1[k*128 + n]; }
    if (i < 128*128){ int n = i/128, k = i%128; g_We2T[i] = We2[k*128 + n]; }
    if (i < 512*128){ int n = i/128, k = i%128; g_WoT[i] = (n < EDIM) ? Wo[k*EDIM + n] : 0.0f; }
}

// -------- layernorm --------
__global__ void ln_kernel(const float* __restrict__ x,
                          const float* __restrict__ g,
                          const float* __restrict__ b){
    int row = blockIdx.x*8 + threadIdx.y;
    if (row >= N_NODES) return;
    int lane = threadIdx.x;
    float4 v = ((const float4*)(x + row*HID))[lane];
    float s = v.x + v.y + v.z + v.w;
    #pragma unroll
    for (int o = 16; o > 0; o >>= 1) s += __shfl_xor_sync(0xffffffffu, s, o);
    float mu = s * (1.0f/HID);
    float dx = v.x-mu, dy = v.y-mu, dz = v.z-mu, dw = v.w-mu;
    float q = dx*dx + dy*dy + dz*dz + dw*dw;
    #pragma unroll
    for (int o = 16; o > 0; o >>= 1) q += __shfl_xor_sync(0xffffffffu, q, o);
    float rstd = rsqrtf(q*(1.0f/HID) + 1e-5f);
    float4 gg = ((const float4*)g)[lane];
    float4 bb = ((const float4*)b)[lane];
    float4 o4;
    o4.x = dx*rstd*gg.x + bb.x;
    o4.y = dy*rstd*gg.y + bb.y;
    o4.z = dz*rstd*gg.z + bb.z;
    o4.w = dw*rstd*gg.w + bb.w;
    ((float4*)(g_xh + row*HID))[lane] = o4;
}

// ============ pipelined MMA edge kernels: 128x128 tile, 8 warps (2x4), warp tile 64x32 ============

#define MMA_TILE(tA, tB) do { \
    _Pragma("unroll") \
    for (int k0 = 0; k0 < 32; k0 += 8){ \
        uint32_t a[4][4]; \
        _Pragma("unroll") \
        for (int mt = 0; mt < 4; mt++){ \
            int R0 = wm + mt*16 + lr; \
            a[mt][0] = (tA)[swzi(R0,     k0 + lc)]; \
            a[mt][1] = (tA)[swzi(R0 + 8, k0 + lc)]; \
            a[mt][2] = (tA)[swzi(R0,     k0 + 4 + lc)]; \
            a[mt][3] = (tA)[swzi(R0 + 8, k0 + 4 + lc)]; \
        } \
        _Pragma("unroll") \
        for (int nt = 0; nt < 4; nt++){ \
            int n = wn + nt*8 + lr; \
            uint32_t b0 = (tB)[swzi(n, k0 + lc)]; \
            uint32_t b1 = (tB)[swzi(n, k0 + 4 + lc)]; \
            _Pragma("unroll") \
            for (int mt = 0; mt < 4; mt++) mma8(acc[mt][nt], a[mt], b0, b1); \
        } \
    } \
} while(0)

// -------- edge MLP layer 1: m1 = silu([xh_i|xh_j|w] @ We1 + be1) --------
__global__ void __launch_bounds__(256, 2) edge_mlp1_mma(const float* __restrict__ be1,
                                                        const float* __restrict__ weight,
                                                        const int* __restrict__ ei){
    extern __shared__ uint32_t dynsm[];
    __shared__ float sBias[128];
    __shared__ int s_ii[128], s_jj[128];
    const int tid = threadIdx.x;
    const int e0  = blockIdx.x*128;
    if (tid < 128){
        s_ii[tid] = ei[e0 + tid];
        s_jj[tid] = ei[N_EDGES + e0 + tid];
        sBias[tid] = be1[tid];
    }
    __syncthreads();
    const uint32_t sbase = smem_u32(dynsm);
    const int lane = tid & 31, lr = lane >> 2, lc = lane & 3;
    const int wid = tid >> 5;
    const int wm = (wid & 1)*64, wn = (wid >> 1)*32;
    float acc[4][4][4];
    #pragma unroll
    for (int i = 0; i < 4; i++)
        #pragma unroll
        for (int j = 0; j < 4; j++){ acc[i][j][0]=0; acc[i][j][1]=0; acc[i][j][2]=0; acc[i][j][3]=0; }

    const int lr8 = tid >> 3, lc8 = tid & 7;

    #define ISSUE1(st, kt) do { \
        uint32_t ab = sbase + (uint32_t)(st)*(STAGE_WORDS*4); \
        uint32_t bb = sbase + NSTAGE*(STAGE_WORDS*4) + (uint32_t)(st)*(STAGE_WORDS*4); \
        _Pragma("unroll") \
        for (int i = 0; i < 4; i++){ \
            int r = lr8 + i*32, c = lc8; \
            int kg = (kt) + c*4; \
            const void* srcA; \
            if (kg < HID)        srcA = g_xh + s_ii[r]*HID + kg; \
            else if (kg < 2*HID) srcA = g_xh + s_jj[r]*HID + (kg - HID); \
            else                 srcA = weight + (size_t)(e0 + r)*EDIM + (kg - 2*HID); \
            uint32_t off = (uint32_t)(r*32 + (((c ^ r) & 7) << 2))*4u; \
            CP_ASYNC16(ab + off, srcA); \
            CP_ASYNC16(bb + off, (const void*)(g_WeT1 + (size_t)r*K1 + kg)); \
        } \
        CP_COMMIT(); \
    } while(0)

    const int T = K1/32;   // 21
    ISSUE1(0, 0);
    ISSUE1(1, 32);
    int st = 0;
    for (int t = 0; t < T; t++){
        if (t + 1 < T) CP_WAIT(1); else CP_WAIT(0);
        __syncthreads();
        if (t + 2 < T){
            int s2 = st + 2; if (s2 >= NSTAGE) s2 -= NSTAGE;
            ISSUE1(s2, (t+2)*32);
        }
        const uint32_t* tA = dynsm + st*STAGE_WORDS;
        const uint32_t* tB = dynsm + NSTAGE*STAGE_WORDS + st*STAGE_WORDS;
        MMA_TILE(tA, tB);
        if (++st == NSTAGE) st = 0;
    }
    #undef ISSUE1
    #pragma unroll
    for (int mt = 0; mt < 4; mt++){
        int r1 = wm + mt*16 + lr;
        #pragma unroll
        for (int nt = 0; nt < 4; nt++){
            int c = wn + nt*8 + lc*2;
            float2 v1, v2;
            v1.x = silu_f(acc[mt][nt][0] + sBias[c]);
            v1.y = silu_f(acc[mt][nt][1] + sBias[c+1]);
            v2.x = silu_f(acc[mt][nt][2] + sBias[c]);
            v2.y = silu_f(acc[mt][nt][3] + sBias[c+1]);
            *(float2*)(g_m + (size_t)(e0 + r1)*HID + c) = v1;
            *(float2*)(g_m + (size_t)(e0 + r1 + 8)*HID + c) = v2;
        }
    }
}

// -------- edge MLP layer 2 + attention + gated message + segment-sum --------
__global__ void __launch_bounds__(256, 2) edge_mlp2_mma(const float* __restrict__ be2,
                                                        const float* __restrict__ Wa,
                                                        const float* __restrict__ ba,
                                                        const int* __restrict__ ei){
    extern __shared__ uint32_t dynsm[];
    __shared__ float sBias[128], sWa[128], s_att[128];
    __shared__ int s_ii[128];
    const int tid = threadIdx.x;
    const int e0  = blockIdx.x*128;
    if (tid < 128){
        s_ii[tid] = ei[e0 + tid];
        sBias[tid] = be2[tid];
        sWa[tid] = Wa[tid];
        s_att[tid] = 0.0f;
    }
    __syncthreads();
    const uint32_t sbase = smem_u32(dynsm);
    const int lane = tid & 31, lr = lane >> 2, lc = lane & 3;
    const int wid = tid >> 5;
    const int wm = (wid & 1)*64, wn = (wid >> 1)*32;
    float acc[4][4][4];
    #pragma unroll
    for (int i = 0; i < 4; i++)
        #pragma unroll
        for (int j = 0; j < 4; j++){ acc[i][j][0]=0; acc[i][j][1]=0; acc[i][j][2]=0; acc[i][j][3]=0; }

    const int lr8 = tid >> 3, lc8 = tid & 7;

    #define ISSUE2(st, kt) do { \
        uint32_t ab = sbase + (uint32_t)(st)*(STAGE_WORDS*4); \
        uint32_t bb = sbase + NSTAGE*(STAGE_WORDS*4) + (uint32_t)(st)*(STAGE_WORDS*4); \
        _Pragma("unroll") \
        for (int i = 0; i < 4; i++){ \
            int r = lr8 + i*32, c = lc8; \
            int kg = (kt) + c*4; \
            uint32_t off = (uint32_t)(r*32 + (((c ^ r) & 7) << 2))*4u; \
            CP_ASYNC16(ab + off, (const void*)(g_m + (size_t)(e0 + r)*HID + kg)); \
            CP_ASYNC16(bb + off, (const void*)(g_We2T + (size_t)r*HID + kg)); \
        } \
        CP_COMMIT(); \
    } while(0)

    ISSUE2(0, 0);
    ISSUE2(1, 32);
    int st = 0;
    for (int t = 0; t < 4; t++){
        if (t + 1 < 4) CP_WAIT(1); else CP_WAIT(0);
        __syncthreads();
        if (t + 2 < 4){
            int s2 = st + 2; if (s2 >= NSTAGE) s2 -= NSTAGE;
            ISSUE2(s2, (t+2)*32);
        }
        const uint32_t* tA = dynsm + st*STAGE_WORDS;
        const uint32_t* tB = dynsm + NSTAGE*STAGE_WORDS + st*STAGE_WORDS;
        MMA_TILE(tA, tB);
        if (++st == NSTAGE) st = 0;
    }
    #undef ISSUE2
    // m2 = silu(acc + bias); attention partial dots
    #pragma unroll
    for (int mt = 0; mt < 4; mt++){
        float p0 = 0.0f, p1 = 0.0f;
        #pragma unroll
        for (int nt = 0; nt < 4; nt++){
            int c = wn + nt*8 + lc*2;
            float wa0 = sWa[c], wa1 = sWa[c+1];
            float v0 = silu_f(acc[mt][nt][0] + sBias[c]);
            float v1 = silu_f(acc[mt][nt][1] + sBias[c+1]);
            float v2 = silu_f(acc[mt][nt][2] + sBias[c]);
            float v3 = silu_f(acc[mt][nt][3] + sBias[c+1]);
            acc[mt][nt][0]=v0; acc[mt][nt][1]=v1; acc[mt][nt][2]=v2; acc[mt][nt][3]=v3;
            p0 += v0*wa0 + v1*wa1;
            p1 += v2*wa0 + v3*wa1;
        }
        atomicAdd(&s_att[wm + mt*16 + lr], p0);
        atomicAdd(&s_att[wm + mt*16 + lr + 8], p1);
    }
    __syncthreads();
    const float ba0 = ba[0];
    #pragma unroll
    for (int mt = 0; mt < 4; mt++){
        int r1 = wm + mt*16 + lr, r2 = r1 + 8;
        float att1 = silu_f(s_att[r1] + ba0);
        float att2 = silu_f(s_att[r2] + ba0);
        int n1 = s_ii[r1], n2 = s_ii[r2];
        #pragma unroll
        for (int nt = 0; nt < 4; nt++){
            int c = wn + nt*8 + lc*2;
            float2 v1, v2;
            v1.x = acc[mt][nt][0]*att1; v1.y = acc[mt][nt][1]*att1;
            v2.x = acc[mt][nt][2]*att2; v2.y = acc[mt][nt][3]*att2;
            *(float2*)(g_m + (size_t)(e0 + r1)*HID + c) = v1;
            *(float2*)(g_m + (size_t)(e0 + r2)*HID + c) = v2;
            asm volatile("red.global.add.v2.f32 [%0], {%1,%2};"
                         :: "l"(g_agg + (size_t)n1*HID + c), "f"(v1.x), "f"(v1.y) : "memory");
            asm volatile("red.global.add.v2.f32 [%0], {%1,%2};"
                         :: "l"(g_agg + (size_t)n2*HID + c), "f"(v2.x), "f"(v2.y) : "memory");
        }
    }
    if (tid < 128) atomicAdd(&g_cnt[s_ii[tid]], 1.0f);
}

// -------- edge out: edgeh = weight + silu(m_ij @ Wo + bo); N tiled by gridDim.y --------
__global__ void __launch_bounds__(256, 2) edge_out_mma(const float* __restrict__ bo,
                                                       const float* __restrict__ weight,
                                                       float* __restrict__ out){
    extern __shared__ uint32_t dynsm[];
    __shared__ float sBias[128];
    const int tid = threadIdx.x;
    const int e0  = blockIdx.x*128;
    const int nb  = blockIdx.y*128;
    if (tid < 128) sBias[tid] = (nb + tid < EDIM) ? bo[nb + tid] : 0.0f;
    __syncthreads();
    const uint32_t sbase = smem_u32(dynsm);
    const int lane = tid & 31, lr = lane >> 2, lc = lane & 3;
    const int wid = tid >> 5;
    const int wm = (wid & 1)*64, wn = (wid >> 1)*32;
    float acc[4][4][4];
    #pragma unroll
    for (int i = 0; i < 4; i++)
        #pragma unroll
        for (int j = 0; j < 4; j++){ acc[i][j][0]=0; acc[i][j][1]=0; acc[i][j][2]=0; acc[i][j][3]=0; }

    const int lr8 = tid >> 3, lc8 = tid & 7;

    #define ISSUE3(st, kt) do { \
        uint32_t ab = sbase + (uint32_t)(st)*(STAGE_WORDS*4); \
        uint32_t bb = sbase + NSTAGE*(STAGE_WORDS*4) + (uint32_t)(st)*(STAGE_WORDS*4); \
        _Pragma("unroll") \
        for (int i = 0; i < 4; i++){ \
            int r = lr8 + i*32, c = lc8; \
            int kg = (kt) + c*4; \
            uint32_t off = (uint32_t)(r*32 + (((c ^ r) & 7) << 2))*4u; \
            CP_ASYNC16(ab + off, (const void*)(g_m + (size_t)(e0 + r)*HID + kg)); \
            CP_ASYNC16(bb + off, (const void*)(g_WoT + (size_t)(nb + r)*HID + kg)); \
        } \
        CP_COMMIT(); \
    } while(0)

    ISSUE3(0, 0);
    ISSUE3(1, 32);
    int st = 0;
    for (int t = 0; t < 4; t++){
        if (t + 1 < 4) CP_WAIT(1); else CP_WAIT(0);
        __syncthreads();
        if (t + 2 < 4){
            int s2 = st + 2; if (s2 >= NSTAGE) s2 -= NSTAGE;
            ISSUE3(s2, (t+2)*32);
        }
        const uint32_t* tA = dynsm + st*STAGE_WORDS;
        const uint32_t* tB = dynsm + NSTAGE*STAGE_WORDS + st*STAGE_WORDS;
        MMA_TILE(tA, tB);
        if (++st == NSTAGE) st = 0;
    }
    #undef ISSUE3
    #pragma unroll
    for (int mt = 0; mt < 4; mt++){
        int r1 = e0 + wm + mt*16 + lr;
        #pragma unroll
        for (int nt = 0; nt < 4; nt++){
            int c = wn + nt*8 + lc*2;
            int g = nb + c;
            if (g < EDIM){
                float2 w1 = *(const float2*)(weight + (size_t)r1*EDIM + g);
                float2 w2 = *(const float2*)(weight + (size_t)(r1+8)*EDIM + g);
                float2 v1, v2;
                v1.x = w1.x + silu_f(acc[mt][nt][0] + sBias[c]);
                v1.y = w1.y + silu_f(acc[mt][nt][1] + sBias[c+1]);
                v2.x = w2.x + silu_f(acc[mt][nt][2] + sBias[c]);
                v2.y = w2.y + silu_f(acc[mt][nt][3] + sBias[c+1]);
                *(float2*)(out + X_OUT_ELEMS + (size_t)r1*EDIM + g) = v1;
                *(float2*)(out + X_OUT_ELEMS + (size_t)(r1+8)*EDIM + g) = v2;
            }
        }
    }
}

// ================= scalar node kernels =================
__global__ void __launch_bounds__(256) node_mlp1_kernel(const float* __restrict__ Wn1,
                                                        const float* __restrict__ bn1){
    __shared__ float sA[64*33];
    __shared__ float sB[32*128];
    __shared__ float s_inv[64];
    const int tid = threadIdx.x;
    const int r0  = blockIdx.x*64;
    if (tid < 64){
        int node = min(r0 + tid, N_NODES - 1);
        float c = g_cnt[node];
        s_inv[tid] = 1.0f / ((c == 0.0f) ? 1.0f : c);
    }
    __syncthreads();
    const int m0 = (tid >> 5)*8;
    const int n0 = (tid & 31)*4;
    float acc[8][4];
    #pragma unroll
    for (int i = 0; i < 8; i++){ acc[i][0]=0; acc[i][1]=0; acc[i][2]=0; acc[i][3]=0; }

    for (int kt = 0; kt < 2*HID; kt += 32){
        #pragma unroll
        for (int i = 0; i < 8; i++){
            int idx = tid + i*256;
            int r = idx >> 5, k = idx & 31;
            int kg = kt + k;
            int node = min(r0 + r, N_NODES - 1);
            float v = (kg < HID) ? g_xh[node*HID + kg]
                                 : g_agg[node*HID + (kg - HID)] * s_inv[r];
            sA[r*33 + k] = v;
        }
        #pragma unroll
        for (int i = 0; i < 16; i++){
            int idx = tid + i*256;
            int k = idx >> 7, n = idx & 127;
            sB[k*128 + n] = Wn1[(kt + k)*128 + n];
        }
        __syncthreads();
        #pragma unroll
        for (int kk = 0; kk < 32; kk++){
            float4 bv = *(const float4*)&sB[kk*128 + n0];
            #pragma unroll
            for (int i = 0; i < 8; i++){
                float a = sA[(m0+i)*33 + kk];
                acc[i][0] += a*bv.x; acc[i][1] += a*bv.y;
                acc[i][2] += a*bv.z; acc[i][3] += a*bv.w;
            }
        }
        __syncthreads();
    }
    float4 bias = *(const float4*)&bn1[n0];
    #pragma unroll
    for (int i = 0; i < 8; i++){
        int row = r0 + m0 + i;
        if (row < N_NODES){
            float4 o;
            o.x = silu_f(acc[i][0] + bias.x);
            o.y = silu_f(acc[i][1] + bias.y);
            o.z = silu_f(acc[i][2] + bias.z);
            o.w = silu_f(acc[i][3] + bias.w);
            *(float4*)&g_n1[row*HID + n0] = o;
        }
    }
}

__global__ void __launch_bounds__(256) node_mlp2_kernel(const float* __restrict__ Wn2,
                                                        const float* __restrict__ bn2,
                                                        float* __restrict__ out){
    __shared__ float sA[64*33];
    __shared__ float sB[32*128];
    const int tid = threadIdx.x;
    const int r0  = blockIdx.x*64;
    const int m0 = (tid >> 5)*8;
    const int n0 = (tid & 31)*4;
    float acc[8][4];
    #pragma unroll
    for (int i = 0; i < 8; i++){ acc[i][0]=0; acc[i][1]=0; acc[i][2]=0; acc[i][3]=0; }

    for (int kt = 0; kt < HID; kt += 32){
        #pragma unroll
        for (int i = 0; i < 8; i++){
            int idx = tid + i*256;
            int r = idx >> 5, k = idx & 31;
            int node = min(r0 + r, N_NODES - 1);
            sA[r*33 + k] = g_n1[node*HID + kt + k];
        }
        #pragma unroll
        for (int i = 0; i < 16; i++){
            int idx = tid + i*256;
            int k = idx >> 7, n = idx & 127;
            sB[k*128 + n] = Wn2[(kt + k)*128 + n];
        }
        __syncthreads();
        #pragma unroll
        for (int kk = 0; kk < 32; kk++){
            float4 bv = *(const float4*)&sB[kk*128 + n0];
            #pragma unroll
            for (int i = 0; i < 8; i++){
                float a = sA[(m0+i)*33 + kk];
                acc[i][0] += a*bv.x; acc[i][1] += a*bv.y;
                acc[i][2] += a*bv.z; acc[i][3] += a*bv.w;
            }
        }
        __syncthreads();
    }
    float4 bias = *(const float4*)&bn2[n0];
    #pragma unroll
    for (int i = 0; i < 8; i++){
        int row = r0 + m0 + i;
        if (row < N_NODES){
            float4 xh4 = *(const float4*)&g_xh[row*HID + n0];
            float4 o;
            o.x = xh4.x + silu_f(acc[i][0] + bias.x);
            o.y = xh4.y + silu_f(acc[i][1] + bias.y);
            o.z = xh4.z + silu_f(acc[i][2] + bias.z);
            o.w = xh4.w + silu_f(acc[i][3] + bias.w);
            *(float4*)&out[row*HID + n0] = o;
        }
    }
}

extern "C" void kernel_launch(void* const* d_in, const int* in_sizes, int n_in,
                              void* d_out, int out_size){
    const float* x    = (const float*)d_in[0];
    const float* wgt  = (const float*)d_in[1];
    const float* ln_g = (const float*)d_in[2];
    const float* ln_b = (const float*)d_in[3];
    const float* We1  = (const float*)d_in[4];
    const float* be1  = (const float*)d_in[5];
    const float* We2  = (const float*)d_in[6];
    const float* be2  = (const float*)d_in[7];
    const float* Wa   = (const float*)d_in[8];
    const float* ba   = (const float*)d_in[9];
    const float* Wn1  = (const float*)d_in[10];
    const float* bn1  = (const float*)d_in[11];
    const float* Wn2  = (const float*)d_in[12];
    const float* bn2  = (const float*)d_in[13];
    const float* Wo   = (const float*)d_in[14];
    const float* bo   = (const float*)d_in[15];
    const int*   ei   = (const int*)d_in[16];
    float* out = (float*)d_out;

    cudaFuncSetAttribute(edge_mlp1_mma, cudaFuncAttributeMaxDynamicSharedMemorySize, SMEM_BYTES);
    cudaFuncSetAttribute(edge_mlp2_mma, cudaFuncAttributeMaxDynamicSharedMemorySize, SMEM_BYTES);
    cudaFuncSetAttribute(edge_out_mma,  cudaFuncAttributeMaxDynamicSharedMemorySize, SMEM_BYTES);

    setup_kernel<<<(N_NODES*HID + 255)/256, 256>>>(We1, We2, Wo);
    ln_kernel<<<(N_NODES + 7)/8, dim3(32, 8)>>>(x, ln_g, ln_b);
    edge_mlp1_mma<<<N_EDGES/128, 256, SMEM_BYTES>>>(be1, wgt, ei);
    edge_mlp2_mma<<<N_EDGES/128, 256, SMEM_BYTES>>>(be2, Wa, ba, ei);
    node_mlp1_kernel<<<(N_NODES + 63)/64, 256>>>(Wn1, bn1);
    node_mlp2_kernel<<<(N_NODES + 63)/64, 256>>>(Wn2, bn2, out);
    edge_out_mma<<<dim3(N_EDGES/128, 4), 256, SMEM_BYTES>>>(bo, wgt, out);
}